// round 3
// baseline (speedup 1.0000x reference)
#include <cuda_runtime.h>
#include <math.h>

#define NN 2048
#define NH 8

// ---------------- static scratch (allocation-free rule) ----------------
__device__ float g_h[(size_t)NH * NN * 512];        // per-head hidden  [H,N,hid<=512]
__device__ float g_hcat[(size_t)NN * NH * 512];     // [N, H*hid<=4096]
__device__ float g_ho[(size_t)NN * 512];            // [N, fout<=384]
__device__ float g_part[(size_t)4 * NN * 384];      // split-K partials
__device__ float g_xA[(size_t)NN * 512];            // ping-pong features
__device__ float g_xB[(size_t)NN * 512];
__device__ float g_s1[NH * NN];
__device__ float g_s2[NH * NN];
__device__ float g_t1[NN];
__device__ float g_t2[NN];
__device__ int   g_deg[NN];
__device__ int   g_rowptr[NN + 1];
__device__ int   g_cols[(size_t)NN * NN];           // worst-case capacity

// ---------------- CSR build (deterministic, no atomics) ----------------
__global__ void deg_kernel(const float* __restrict__ adj, int* __restrict__ deg) {
  int w = (blockIdx.x * blockDim.x + threadIdx.x) >> 5;
  int lane = threadIdx.x & 31;
  if (w >= NN) return;
  const float* row = adj + (size_t)w * NN;
  int c = 0;
  for (int j = lane; j < NN; j += 32) c += (row[j] > 0.0f);
  for (int o = 16; o; o >>= 1) c += __shfl_down_sync(0xffffffffu, c, o);
  if (lane == 0) deg[w] = c;
}

__global__ void scan_kernel(const int* __restrict__ deg, int* __restrict__ rowptr) {
  __shared__ int p[1024];
  int t = threadIdx.x;
  int a = deg[2 * t];
  int b = deg[2 * t + 1];
  p[t] = a + b;
  __syncthreads();
  for (int off = 1; off < 1024; off <<= 1) {
    int v = (t >= off) ? p[t - off] : 0;
    __syncthreads();
    p[t] += v;
    __syncthreads();
  }
  int excl = (t == 0) ? 0 : p[t - 1];
  rowptr[2 * t] = excl;
  rowptr[2 * t + 1] = excl + a;
  if (t == 1023) rowptr[NN] = p[1023];
}

__global__ void fill_kernel(const float* __restrict__ adj,
                            const int* __restrict__ rowptr,
                            int* __restrict__ cols) {
  int w = (blockIdx.x * blockDim.x + threadIdx.x) >> 5;
  int lane = threadIdx.x & 31;
  if (w >= NN) return;
  const float* row = adj + (size_t)w * NN;
  int cur = rowptr[w];
  for (int j0 = 0; j0 < NN; j0 += 32) {
    float v = row[j0 + lane];
    unsigned mask = __ballot_sync(0xffffffffu, v > 0.0f);
    if (v > 0.0f) {
      int pos = __popc(mask & ((1u << lane) - 1u));
      cols[cur + pos] = j0 + lane;
    }
    cur += __popc(mask);
  }
}

// ---------------- tiled SGEMM: 128x128 tile, 8x8 microtile, k-step 8 ----------------
// Double-buffered smem, 1 barrier per k-step.
// C[batch] (+ optional split-K chunking over blockIdx.z).
// Requires: M%128==0, Nn%128==0, (K/kChunks)%8==0.
// A row-major [M,K], B row-major [K,Nn].
__global__ void __launch_bounds__(256) sgemm128(
    const float* __restrict__ A, const float* __restrict__ B, float* __restrict__ C,
    int M, int Nn, int K,
    long long strideB, long long strideC,     // per-batch strides
    int kChunks, long long chunkStride) {     // split-K partial-output stride
  int z = blockIdx.z;
  int batch = z / kChunks;
  int chunk = z % kChunks;
  const float* Bh = B + (long long)batch * strideB;
  float* Ch = C + (long long)batch * strideC + (long long)chunk * chunkStride;
  int Kc = K / kChunks;
  int kbeg = chunk * Kc;
  int kend = kbeg + Kc;

  __shared__ float As[2][8][128];   // transposed A tile: As[buf][k][row]
  __shared__ float Bs[2][8][128];
  int tx = threadIdx.x;
  int row0 = blockIdx.y * 128, col0 = blockIdx.x * 128;
  int tx2 = tx & 15, ty = tx >> 4;

  // global load indices
  int a_r = tx >> 1, a_c = (tx & 1) << 2;    // A: 128 rows x 2 float4
  int b_r = tx >> 5, b_c = (tx & 31) << 2;   // B: 8 rows x 32 float4
  const float* Aptr = A + (size_t)(row0 + a_r) * K + a_c;
  const float* Bptr = Bh + (size_t)b_r * Nn + col0 + b_c;

  float acc[8][8];
#pragma unroll
  for (int i = 0; i < 8; i++)
#pragma unroll
    for (int j = 0; j < 8; j++) acc[i][j] = 0.0f;

  // prologue: load first tile into buf 0
  float4 av = *(const float4*)(Aptr + kbeg);
  float4 bv = *(const float4*)(Bptr + (size_t)kbeg * Nn);
  As[0][a_c + 0][a_r] = av.x;
  As[0][a_c + 1][a_r] = av.y;
  As[0][a_c + 2][a_r] = av.z;
  As[0][a_c + 3][a_r] = av.w;
  *(float4*)&Bs[0][b_r][b_c] = bv;
  __syncthreads();

  int p = 0;
  for (int k0 = kbeg; k0 < kend; k0 += 8) {
    int knext = k0 + 8;
    bool more = knext < kend;
    if (more) {  // prefetch next tile into registers (overlaps with FFMA burst)
      av = *(const float4*)(Aptr + knext);
      bv = *(const float4*)(Bptr + (size_t)knext * Nn);
    }
#pragma unroll
    for (int kk = 0; kk < 8; kk++) {
      float4 a0 = *(const float4*)&As[p][kk][ty << 2];
      float4 a1 = *(const float4*)&As[p][kk][64 + (ty << 2)];
      float4 b0 = *(const float4*)&Bs[p][kk][tx2 << 2];
      float4 b1 = *(const float4*)&Bs[p][kk][64 + (tx2 << 2)];
      float aa[8] = {a0.x, a0.y, a0.z, a0.w, a1.x, a1.y, a1.z, a1.w};
      float bb[8] = {b0.x, b0.y, b0.z, b0.w, b1.x, b1.y, b1.z, b1.w};
#pragma unroll
      for (int i = 0; i < 8; i++)
#pragma unroll
        for (int j = 0; j < 8; j++) acc[i][j] += aa[i] * bb[j];
    }
    if (more) {  // store prefetched tile to the other buffer
      int q = p ^ 1;
      As[q][a_c + 0][a_r] = av.x;
      As[q][a_c + 1][a_r] = av.y;
      As[q][a_c + 2][a_r] = av.z;
      As[q][a_c + 3][a_r] = av.w;
      *(float4*)&Bs[q][b_r][b_c] = bv;
      __syncthreads();
      p = q;
    }
  }

  // write back: rows {ty*4+i, 64+ty*4+i}, cols {tx2*4.., 64+tx2*4..}
#pragma unroll
  for (int ih = 0; ih < 2; ih++) {
#pragma unroll
    for (int i = 0; i < 4; i++) {
      int r = row0 + ih * 64 + (ty << 2) + i;
      int ai = ih * 4 + i;
      float4 o0 = make_float4(acc[ai][0], acc[ai][1], acc[ai][2], acc[ai][3]);
      float4 o1 = make_float4(acc[ai][4], acc[ai][5], acc[ai][6], acc[ai][7]);
      *(float4*)(Ch + (size_t)r * Nn + col0 + (tx2 << 2)) = o0;
      *(float4*)(Ch + (size_t)r * Nn + col0 + 64 + (tx2 << 2)) = o1;
    }
  }
}

// ---------------- split-K reduce (fixed order -> deterministic) ----------------
__global__ void reduce4(const float* __restrict__ part, float* __restrict__ out,
                        long long n, long long stride) {
  long long i = (long long)blockIdx.x * blockDim.x + threadIdx.x;
  if (i >= n) return;
  out[i] = ((part[i] + part[i + stride]) + part[i + 2 * stride]) + part[i + 3 * stride];
}

// ---------------- s1/s2: per-row dual dot with attention vector ----------------
__global__ void rowdot2(const float* __restrict__ feat, const float* __restrict__ a,
                        float* __restrict__ o1, float* __restrict__ o2, int D) {
  int h = blockIdx.y;
  int w = blockIdx.x * (blockDim.x >> 5) + (threadIdx.x >> 5);
  int lane = threadIdx.x & 31;
  if (w >= NN) return;
  const float* f = feat + ((size_t)h * NN + w) * D;
  const float* a1 = a + (size_t)h * 2 * D;
  const float* a2 = a1 + D;
  float d1 = 0.0f, d2 = 0.0f;
  for (int d = lane; d < D; d += 32) {
    float v = f[d];
    d1 += v * a1[d];
    d2 += v * a2[d];
  }
  for (int o = 16; o; o >>= 1) {
    d1 += __shfl_down_sync(0xffffffffu, d1, o);
    d2 += __shfl_down_sync(0xffffffffu, d2, o);
  }
  if (lane == 0) {
    o1[(size_t)h * NN + w] = d1;
    o2[(size_t)h * NN + w] = d2;
  }
}

// ---------------- sparse masked softmax attention + aggregate + elu ----------------
// block = (node i, head h). D multiple of 128 (128/256/384/512).
__global__ void __launch_bounds__(128) attn_agg(
    const int* __restrict__ rowptr, const int* __restrict__ cols,
    const float* __restrict__ s1, const float* __restrict__ s2,
    const float* __restrict__ feat, float* __restrict__ out,
    int D, long long outRowStride) {
  int i = blockIdx.x, h = blockIdx.y;
  int t = threadIdx.x;
  __shared__ float red[128];
  __shared__ float shw[128];
  __shared__ int shc[128];
  float s1i = s1[(size_t)h * NN + i];
  const float* s2h = s2 + (size_t)h * NN;
  const float* fh = feat + (size_t)h * NN * D;
  int start = rowptr[i], end = rowptr[i + 1];

  // pass 1: row max of leaky-relu scores over neighbors
  float m = -1e30f;
  for (int e = start + t; e < end; e += 128) {
    float z = s1i + s2h[cols[e]];
    z = z > 0.0f ? z : 0.2f * z;
    m = fmaxf(m, z);
  }
  red[t] = m;
  __syncthreads();
  for (int s = 64; s > 0; s >>= 1) {
    if (t < s) red[t] = fmaxf(red[t], red[t + s]);
    __syncthreads();
  }
  m = red[0];

  // pass 2: chunked weights + weighted feature gather
  int dper = D >> 7;  // D/128 in 1..4
  float acc[4] = {0.0f, 0.0f, 0.0f, 0.0f};
  float dsum = 0.0f;
  for (int c0 = start; c0 < end; c0 += 128) {
    int len = min(128, end - c0);
    __syncthreads();
    if (t < len) {
      int j = cols[c0 + t];
      float z = s1i + s2h[j];
      z = z > 0.0f ? z : 0.2f * z;
      float w = expf(z - m);
      shw[t] = w;
      shc[t] = j;
      dsum += w;
    }
    __syncthreads();
    for (int jj = 0; jj < len; jj++) {
      float w = shw[jj];
      const float* fj = fh + (size_t)shc[jj] * D;
#pragma unroll
      for (int q = 0; q < 4; q++)
        if (q < dper) acc[q] += w * fj[t + (q << 7)];
    }
  }
  __syncthreads();
  red[t] = dsum;
  __syncthreads();
  for (int s = 64; s > 0; s >>= 1) {
    if (t < s) red[t] += red[t + s];
    __syncthreads();
  }
  float inv = 1.0f / red[0];
  float* orow = out + (size_t)i * outRowStride + (size_t)h * D;
  for (int q = 0; q < dper; q++) {
    float v = acc[q] * inv;
    orow[t + (q << 7)] = v > 0.0f ? v : expm1f(v);  // elu
  }
}

// ---------------- orchestration ----------------
extern "C" void kernel_launch(void* const* d_in, const int* in_sizes, int n_in,
                              void* d_out, int out_size) {
  (void)in_sizes; (void)n_in; (void)out_size;
  const float* x = (const float*)d_in[0];
  const float* adj = (const float*)d_in[1];

  float *p_h, *p_hcat, *p_ho, *p_part, *p_xA, *p_xB, *p_s1, *p_s2, *p_t1, *p_t2;
  int *p_deg, *p_rowptr, *p_cols;
  cudaGetSymbolAddress((void**)&p_h, g_h);
  cudaGetSymbolAddress((void**)&p_hcat, g_hcat);
  cudaGetSymbolAddress((void**)&p_ho, g_ho);
  cudaGetSymbolAddress((void**)&p_part, g_part);
  cudaGetSymbolAddress((void**)&p_xA, g_xA);
  cudaGetSymbolAddress((void**)&p_xB, g_xB);
  cudaGetSymbolAddress((void**)&p_s1, g_s1);
  cudaGetSymbolAddress((void**)&p_s2, g_s2);
  cudaGetSymbolAddress((void**)&p_t1, g_t1);
  cudaGetSymbolAddress((void**)&p_t2, g_t2);
  cudaGetSymbolAddress((void**)&p_deg, g_deg);
  cudaGetSymbolAddress((void**)&p_rowptr, g_rowptr);
  cudaGetSymbolAddress((void**)&p_cols, g_cols);

  // build CSR of fixed adjacency (cheap; deterministic ordering)
  deg_kernel<<<256, 256>>>(adj, p_deg);
  scan_kernel<<<1, 1024>>>(p_deg, p_rowptr);
  fill_kernel<<<256, 256>>>(adj, p_rowptr, p_cols);

  const int FIN[6]  = {256, 128, 256, 384, 256, 128};
  const int HID[6]  = {128, 256, 512, 512, 256, 128};
  const int FOUT[6] = {128, 256, 384, 256, 128, 256};

  const float* cur = x;
  for (int L = 0; L < 6; L++) {
    const float* Wh = (const float*)d_in[2 + 4 * L + 0];
    const float* ah = (const float*)d_in[2 + 4 * L + 1];
    const float* Wo = (const float*)d_in[2 + 4 * L + 2];
    const float* ao = (const float*)d_in[2 + 4 * L + 3];
    int fin = FIN[L], hid = HID[L], fout = FOUT[L];

    // h[h'] = cur @ Wh[h']   -> [H, N, hid]   (batched over 8 heads)
    sgemm128<<<dim3(hid / 128, NN / 128, NH), 256>>>(
        cur, Wh, p_h, NN, hid, fin,
        (long long)fin * hid, (long long)NN * hid, 1, 0);
    // s1/s2 per head
    rowdot2<<<dim3(NN / 8, NH), 256>>>(p_h, ah, p_s1, p_s2, hid);
    // sparse attention aggregate + elu -> hcat [N, H*hid]
    attn_agg<<<dim3(NN, NH), 128>>>(p_rowptr, p_cols, p_s1, p_s2, p_h, p_hcat,
                                    hid, (long long)NH * hid);
    // ho = hcat @ Wo  -> [N, fout]   via deterministic split-K (4 chunks)
    sgemm128<<<dim3(fout / 128, NN / 128, 4), 256>>>(
        p_hcat, Wo, p_part, NN, fout, NH * hid,
        0, 0, 4, (long long)NN * fout);
    {
      long long n = (long long)NN * fout;
      reduce4<<<(unsigned)((n + 255) / 256), 256>>>(p_part, p_ho, n,
                                                    (long long)NN * fout);
    }
    // output-head scores
    rowdot2<<<dim3(NN / 8, 1), 256>>>(p_ho, ao, p_t1, p_t2, fout);
    // output sparse attention + elu -> next features (or final output)
    float* dst = (L == 5) ? (float*)d_out : ((L & 1) ? p_xB : p_xA);
    attn_agg<<<dim3(NN, 1), 128>>>(p_rowptr, p_cols, p_t1, p_t2, p_ho, dst,
                                   fout, (long long)fout);
    cur = dst;
  }
}

// round 4
// speedup vs baseline: 1.0390x; 1.0390x over previous
#include <cuda_runtime.h>
#include <math.h>

#define NN 2048
#define NH 8

// ---------------- static scratch (allocation-free rule) ----------------
__device__ float g_h[(size_t)NH * NN * 512];        // per-head hidden  [H,N,hid<=512]
__device__ float g_hcat[(size_t)NN * NH * 512];     // [N, H*hid<=4096]
__device__ float g_ho[(size_t)NN * 512];            // [N, fout<=384]
__device__ float g_part[(size_t)8 * NN * 384];      // split-K partials (8 chunks)
__device__ float g_xA[(size_t)NN * 512];            // ping-pong features
__device__ float g_xB[(size_t)NN * 512];
__device__ float g_s1[NH * NN];
__device__ float g_s2[NH * NN];
__device__ float g_t1[NN];
__device__ float g_t2[NN];
__device__ int   g_deg[NN];
__device__ int   g_rowptr[NN + 1];
__device__ int   g_cols[(size_t)NN * NN];           // worst-case capacity

// ---------------- CSR build (deterministic, no atomics) ----------------
__global__ void deg_kernel(const float* __restrict__ adj, int* __restrict__ deg) {
  int w = (blockIdx.x * blockDim.x + threadIdx.x) >> 5;
  int lane = threadIdx.x & 31;
  if (w >= NN) return;
  const float* row = adj + (size_t)w * NN;
  int c = 0;
  for (int j = lane; j < NN; j += 32) c += (row[j] > 0.0f);
  for (int o = 16; o; o >>= 1) c += __shfl_down_sync(0xffffffffu, c, o);
  if (lane == 0) deg[w] = c;
}

__global__ void scan_kernel(const int* __restrict__ deg, int* __restrict__ rowptr) {
  __shared__ int p[1024];
  int t = threadIdx.x;
  int a = deg[2 * t];
  int b = deg[2 * t + 1];
  p[t] = a + b;
  __syncthreads();
  for (int off = 1; off < 1024; off <<= 1) {
    int v = (t >= off) ? p[t - off] : 0;
    __syncthreads();
    p[t] += v;
    __syncthreads();
  }
  int excl = (t == 0) ? 0 : p[t - 1];
  rowptr[2 * t] = excl;
  rowptr[2 * t + 1] = excl + a;
  if (t == 1023) rowptr[NN] = p[1023];
}

__global__ void fill_kernel(const float* __restrict__ adj,
                            const int* __restrict__ rowptr,
                            int* __restrict__ cols) {
  int w = (blockIdx.x * blockDim.x + threadIdx.x) >> 5;
  int lane = threadIdx.x & 31;
  if (w >= NN) return;
  const float* row = adj + (size_t)w * NN;
  int cur = rowptr[w];
  for (int j0 = 0; j0 < NN; j0 += 32) {
    float v = row[j0 + lane];
    unsigned mask = __ballot_sync(0xffffffffu, v > 0.0f);
    if (v > 0.0f) {
      int pos = __popc(mask & ((1u << lane) - 1u));
      cols[cur + pos] = j0 + lane;
    }
    cur += __popc(mask);
  }
}

// ---------------- tiled SGEMM: 128x64 tile, 8x4 microtile, k-step 8 ----------------
// Double-buffered smem, 1 barrier per k-step, 3 CTAs/SM target.
// C[batch] (+ optional split-K chunking over blockIdx.z).
// Requires: M%128==0, Nn%64==0, (K/kChunks)%8==0.
// A row-major [M,K], B row-major [K,Nn].
__global__ void __launch_bounds__(256, 3) sgemm_t(
    const float* __restrict__ A, const float* __restrict__ B, float* __restrict__ C,
    int M, int Nn, int K,
    long long strideB, long long strideC,     // per-batch strides
    int kChunks, long long chunkStride) {     // split-K partial-output stride
  int z = blockIdx.z;
  int batch = z / kChunks;
  int chunk = z % kChunks;
  const float* Bh = B + (long long)batch * strideB;
  float* Ch = C + (long long)batch * strideC + (long long)chunk * chunkStride;
  int Kc = K / kChunks;
  int kbeg = chunk * Kc;
  int kend = kbeg + Kc;

  __shared__ float As[2][8][128];   // transposed A tile: As[buf][k][row]
  __shared__ float Bs[2][8][64];
  int tx = threadIdx.x;
  int row0 = blockIdx.y * 128, col0 = blockIdx.x * 64;
  int tc = tx & 15, tr = tx >> 4;

  // global load indices
  int a_r = tx >> 1, a_c = (tx & 1) << 2;    // A: 128 rows x 2 float4 (all 256 thr)
  int b_r = tx >> 4, b_c = (tx & 15) << 2;   // B: 8 rows x 16 float4 (thr < 128)
  const float* Aptr = A + (size_t)(row0 + a_r) * K + a_c;
  const float* Bptr = Bh + (size_t)b_r * Nn + col0 + b_c;
  bool bload = tx < 128;

  float acc[8][4];
#pragma unroll
  for (int i = 0; i < 8; i++)
#pragma unroll
    for (int j = 0; j < 4; j++) acc[i][j] = 0.0f;

  // prologue: load first tile into buf 0
  float4 av = *(const float4*)(Aptr + kbeg);
  float4 bv;
  if (bload) bv = *(const float4*)(Bptr + (size_t)kbeg * Nn);
  As[0][a_c + 0][a_r] = av.x;
  As[0][a_c + 1][a_r] = av.y;
  As[0][a_c + 2][a_r] = av.z;
  As[0][a_c + 3][a_r] = av.w;
  if (bload) *(float4*)&Bs[0][b_r][b_c] = bv;
  __syncthreads();

  int p = 0;
  for (int k0 = kbeg; k0 < kend; k0 += 8) {
    int knext = k0 + 8;
    bool more = knext < kend;
    if (more) {  // prefetch next tile into registers (overlaps FFMA burst)
      av = *(const float4*)(Aptr + knext);
      if (bload) bv = *(const float4*)(Bptr + (size_t)knext * Nn);
    }
#pragma unroll
    for (int kk = 0; kk < 8; kk++) {
      float4 a0 = *(const float4*)&As[p][kk][tr << 2];
      float4 a1 = *(const float4*)&As[p][kk][64 + (tr << 2)];
      float4 b0 = *(const float4*)&Bs[p][kk][tc << 2];
      float aa[8] = {a0.x, a0.y, a0.z, a0.w, a1.x, a1.y, a1.z, a1.w};
      float bb[4] = {b0.x, b0.y, b0.z, b0.w};
#pragma unroll
      for (int i = 0; i < 8; i++)
#pragma unroll
        for (int j = 0; j < 4; j++) acc[i][j] += aa[i] * bb[j];
    }
    if (more) {
      int q = p ^ 1;
      As[q][a_c + 0][a_r] = av.x;
      As[q][a_c + 1][a_r] = av.y;
      As[q][a_c + 2][a_r] = av.z;
      As[q][a_c + 3][a_r] = av.w;
      if (bload) *(float4*)&Bs[q][b_r][b_c] = bv;
      __syncthreads();
      p = q;
    }
  }

  // write back: rows {tr*4+i, 64+tr*4+i}, cols col0 + tc*4
#pragma unroll
  for (int ih = 0; ih < 2; ih++) {
#pragma unroll
    for (int i = 0; i < 4; i++) {
      int r = row0 + ih * 64 + (tr << 2) + i;
      int ai = ih * 4 + i;
      float4 o = make_float4(acc[ai][0], acc[ai][1], acc[ai][2], acc[ai][3]);
      *(float4*)(Ch + (size_t)r * Nn + col0 + (tc << 2)) = o;
    }
  }
}

// ---------------- split-K reduce (fixed order -> deterministic) ----------------
__global__ void reduce8(const float* __restrict__ part, float* __restrict__ out,
                        long long n, long long stride) {
  long long i = (long long)blockIdx.x * blockDim.x + threadIdx.x;
  if (i >= n) return;
  float s = part[i];
#pragma unroll
  for (int c = 1; c < 8; c++) s += part[i + c * stride];
  out[i] = s;
}

// ---------------- s1/s2: per-row dual dot with attention vector ----------------
__global__ void rowdot2(const float* __restrict__ feat, const float* __restrict__ a,
                        float* __restrict__ o1, float* __restrict__ o2, int D) {
  int h = blockIdx.y;
  int w = blockIdx.x * (blockDim.x >> 5) + (threadIdx.x >> 5);
  int lane = threadIdx.x & 31;
  if (w >= NN) return;
  const float* f = feat + ((size_t)h * NN + w) * D;
  const float* a1 = a + (size_t)h * 2 * D;
  const float* a2 = a1 + D;
  float d1 = 0.0f, d2 = 0.0f;
  for (int d = lane; d < D; d += 32) {
    float v = f[d];
    d1 += v * a1[d];
    d2 += v * a2[d];
  }
  for (int o = 16; o; o >>= 1) {
    d1 += __shfl_down_sync(0xffffffffu, d1, o);
    d2 += __shfl_down_sync(0xffffffffu, d2, o);
  }
  if (lane == 0) {
    o1[(size_t)h * NN + w] = d1;
    o2[(size_t)h * NN + w] = d2;
  }
}

// ---------------- sparse masked softmax attention + aggregate + elu ----------------
// block = (node i, head h). D multiple of 128 (128/256/384/512).
__global__ void __launch_bounds__(128) attn_agg(
    const int* __restrict__ rowptr, const int* __restrict__ cols,
    const float* __restrict__ s1, const float* __restrict__ s2,
    const float* __restrict__ feat, float* __restrict__ out,
    int D, long long outRowStride) {
  int i = blockIdx.x, h = blockIdx.y;
  int t = threadIdx.x;
  __shared__ float red[128];
  __shared__ float shw[128];
  __shared__ int shc[128];
  float s1i = s1[(size_t)h * NN + i];
  const float* s2h = s2 + (size_t)h * NN;
  const float* fh = feat + (size_t)h * NN * D;
  int start = rowptr[i], end = rowptr[i + 1];

  // pass 1: row max of leaky-relu scores over neighbors
  float m = -1e30f;
  for (int e = start + t; e < end; e += 128) {
    float z = s1i + s2h[cols[e]];
    z = z > 0.0f ? z : 0.2f * z;
    m = fmaxf(m, z);
  }
  red[t] = m;
  __syncthreads();
  for (int s = 64; s > 0; s >>= 1) {
    if (t < s) red[t] = fmaxf(red[t], red[t + s]);
    __syncthreads();
  }
  m = red[0];

  // pass 2: chunked weights + weighted feature gather
  int dper = D >> 7;  // D/128 in 1..4
  float acc[4] = {0.0f, 0.0f, 0.0f, 0.0f};
  float dsum = 0.0f;
  for (int c0 = start; c0 < end; c0 += 128) {
    int len = min(128, end - c0);
    __syncthreads();
    if (t < len) {
      int j = cols[c0 + t];
      float z = s1i + s2h[j];
      z = z > 0.0f ? z : 0.2f * z;
      float w = expf(z - m);
      shw[t] = w;
      shc[t] = j;
      dsum += w;
    }
    __syncthreads();
    for (int jj = 0; jj < len; jj++) {
      float w = shw[jj];
      const float* fj = fh + (size_t)shc[jj] * D;
#pragma unroll
      for (int q = 0; q < 4; q++)
        if (q < dper) acc[q] += w * fj[t + (q << 7)];
    }
  }
  __syncthreads();
  red[t] = dsum;
  __syncthreads();
  for (int s = 64; s > 0; s >>= 1) {
    if (t < s) red[t] += red[t + s];
    __syncthreads();
  }
  float inv = 1.0f / red[0];
  float* orow = out + (size_t)i * outRowStride + (size_t)h * D;
  for (int q = 0; q < dper; q++) {
    float v = acc[q] * inv;
    orow[t + (q << 7)] = v > 0.0f ? v : expm1f(v);  // elu
  }
}

// ---------------- orchestration ----------------
extern "C" void kernel_launch(void* const* d_in, const int* in_sizes, int n_in,
                              void* d_out, int out_size) {
  (void)in_sizes; (void)n_in; (void)out_size;
  const float* x = (const float*)d_in[0];
  const float* adj = (const float*)d_in[1];

  float *p_h, *p_hcat, *p_ho, *p_part, *p_xA, *p_xB, *p_s1, *p_s2, *p_t1, *p_t2;
  int *p_deg, *p_rowptr, *p_cols;
  cudaGetSymbolAddress((void**)&p_h, g_h);
  cudaGetSymbolAddress((void**)&p_hcat, g_hcat);
  cudaGetSymbolAddress((void**)&p_ho, g_ho);
  cudaGetSymbolAddress((void**)&p_part, g_part);
  cudaGetSymbolAddress((void**)&p_xA, g_xA);
  cudaGetSymbolAddress((void**)&p_xB, g_xB);
  cudaGetSymbolAddress((void**)&p_s1, g_s1);
  cudaGetSymbolAddress((void**)&p_s2, g_s2);
  cudaGetSymbolAddress((void**)&p_t1, g_t1);
  cudaGetSymbolAddress((void**)&p_t2, g_t2);
  cudaGetSymbolAddress((void**)&p_deg, g_deg);
  cudaGetSymbolAddress((void**)&p_rowptr, g_rowptr);
  cudaGetSymbolAddress((void**)&p_cols, g_cols);

  // build CSR of fixed adjacency (cheap; deterministic ordering)
  deg_kernel<<<256, 256>>>(adj, p_deg);
  scan_kernel<<<1, 1024>>>(p_deg, p_rowptr);
  fill_kernel<<<256, 256>>>(adj, p_rowptr, p_cols);

  const int FIN[6]  = {256, 128, 256, 384, 256, 128};
  const int HID[6]  = {128, 256, 512, 512, 256, 128};
  const int FOUT[6] = {128, 256, 384, 256, 128, 256};

  const float* cur = x;
  for (int L = 0; L < 6; L++) {
    const float* Wh = (const float*)d_in[2 + 4 * L + 0];
    const float* ah = (const float*)d_in[2 + 4 * L + 1];
    const float* Wo = (const float*)d_in[2 + 4 * L + 2];
    const float* ao = (const float*)d_in[2 + 4 * L + 3];
    int fin = FIN[L], hid = HID[L], fout = FOUT[L];

    // h[h'] = cur @ Wh[h']   -> [H, N, hid]   (batched over 8 heads)
    sgemm_t<<<dim3(hid / 64, NN / 128, NH), 256>>>(
        cur, Wh, p_h, NN, hid, fin,
        (long long)fin * hid, (long long)NN * hid, 1, 0);
    // s1/s2 per head
    rowdot2<<<dim3(NN / 8, NH), 256>>>(p_h, ah, p_s1, p_s2, hid);
    // sparse attention aggregate + elu -> hcat [N, H*hid]
    attn_agg<<<dim3(NN, NH), 128>>>(p_rowptr, p_cols, p_s1, p_s2, p_h, p_hcat,
                                    hid, (long long)NH * hid);
    // ho = hcat @ Wo  -> [N, fout]   via deterministic split-K (8 chunks)
    sgemm_t<<<dim3(fout / 64, NN / 128, 8), 256>>>(
        p_hcat, Wo, p_part, NN, fout, NH * hid,
        0, 0, 8, (long long)NN * fout);
    {
      long long n = (long long)NN * fout;
      reduce8<<<(unsigned)((n + 255) / 256), 256>>>(p_part, p_ho, n,
                                                    (long long)NN * fout);
    }
    // output-head scores
    rowdot2<<<dim3(NN / 8, 1), 256>>>(p_ho, ao, p_t1, p_t2, fout);
    // output sparse attention + elu -> next features (or final output)
    float* dst = (L == 5) ? (float*)d_out : ((L & 1) ? p_xB : p_xA);
    attn_agg<<<dim3(NN, 1), 128>>>(p_rowptr, p_cols, p_t1, p_t2, p_ho, dst,
                                   fout, (long long)fout);
    cur = dst;
  }
}

// round 10
// speedup vs baseline: 1.4483x; 1.3940x over previous
#include <cuda_runtime.h>
#include <cuda_bf16.h>
#include <math.h>
#include <stdint.h>

#define NN 2048
#define NH 8

// ---------------- static scratch (allocation-free rule) ----------------
__device__ float g_h[(size_t)NH * NN * 512];        // per-head hidden  [H,N,hid<=512]
__device__ float g_hcat[(size_t)NN * NH * 512];     // [N, H*hid<=4096]
__device__ float g_ho[(size_t)NN * 512];            // [N, fout<=384]
__device__ float g_part[(size_t)8 * NN * 384];      // split-K partials (8 chunks)
__device__ float g_xA[(size_t)NN * 512];            // ping-pong features
__device__ float g_xB[(size_t)NN * 512];
__device__ float g_s1[NH * NN];
__device__ float g_s2[NH * NN];
__device__ float g_t1[NN];
__device__ float g_t2[NN];
__device__ int   g_deg[NN];
__device__ int   g_rowptr[NN + 1];
__device__ int   g_cols[(size_t)NN * NN];           // worst-case capacity
// split-bf16 operands (16B-aligned for cp.async)
__device__ __align__(256) __nv_bfloat16 g_aH[(size_t)NN * 4096];
__device__ __align__(256) __nv_bfloat16 g_aL[(size_t)NN * 4096];
__device__ __align__(256) __nv_bfloat16 g_bH[2097152];
__device__ __align__(256) __nv_bfloat16 g_bL[2097152];

// ---------------- PTX helpers (sm_80-class only; compiles at compute_103) ---
__device__ __forceinline__ uint32_t smem_u32(const void* p) {
  uint32_t a;
  asm("{ .reg .u64 t; cvta.to.shared.u64 t, %1; cvt.u32.u64 %0, t; }" : "=r"(a) : "l"(p));
  return a;
}
#define CP_ASYNC16(d, s) \
  asm volatile("cp.async.cg.shared.global [%0], [%1], 16;" :: "r"(d), "l"(s) : "memory")
#define CP_COMMIT() asm volatile("cp.async.commit_group;" ::: "memory")
#define CP_WAIT0() asm volatile("cp.async.wait_group 0;" ::: "memory")
#define CP_WAIT1() asm volatile("cp.async.wait_group 1;" ::: "memory")
#define LDMX4(r0, r1, r2, r3, a) \
  asm volatile("ldmatrix.sync.aligned.m8n8.x4.shared.b16 {%0,%1,%2,%3}, [%4];" \
               : "=r"(r0), "=r"(r1), "=r"(r2), "=r"(r3) : "r"(a))
#define LDMX2(r0, r1, a) \
  asm volatile("ldmatrix.sync.aligned.m8n8.x2.shared.b16 {%0,%1}, [%2];" \
               : "=r"(r0), "=r"(r1) : "r"(a))
#define MMA16816(c, a, b) \
  asm volatile( \
      "mma.sync.aligned.m16n8k16.row.col.f32.bf16.bf16.f32 " \
      "{%0,%1,%2,%3}, {%4,%5,%6,%7}, {%8,%9}, {%0,%1,%2,%3};" \
      : "+f"((c)[0]), "+f"((c)[1]), "+f"((c)[2]), "+f"((c)[3]) \
      : "r"((a)[0]), "r"((a)[1]), "r"((a)[2]), "r"((a)[3]), "r"((b)[0]), "r"((b)[1]))

// ---------------- CSR build (deterministic, no atomics) ----------------
__global__ void deg_kernel(const float* __restrict__ adj, int* __restrict__ deg) {
  int w = (blockIdx.x * blockDim.x + threadIdx.x) >> 5;
  int lane = threadIdx.x & 31;
  if (w >= NN) return;
  const float* row = adj + (size_t)w * NN;
  int c = 0;
  for (int j = lane; j < NN; j += 32) c += (row[j] > 0.0f);
  for (int o = 16; o; o >>= 1) c += __shfl_down_sync(0xffffffffu, c, o);
  if (lane == 0) deg[w] = c;
}

__global__ void scan_kernel(const int* __restrict__ deg, int* __restrict__ rowptr) {
  __shared__ int p[1024];
  int t = threadIdx.x;
  int a = deg[2 * t];
  int b = deg[2 * t + 1];
  p[t] = a + b;
  __syncthreads();
  for (int off = 1; off < 1024; off <<= 1) {
    int v = (t >= off) ? p[t - off] : 0;
    __syncthreads();
    p[t] += v;
    __syncthreads();
  }
  int excl = (t == 0) ? 0 : p[t - 1];
  rowptr[2 * t] = excl;
  rowptr[2 * t + 1] = excl + a;
  if (t == 1023) rowptr[NN] = p[1023];
}

__global__ void fill_kernel(const float* __restrict__ adj,
                            const int* __restrict__ rowptr,
                            int* __restrict__ cols) {
  int w = (blockIdx.x * blockDim.x + threadIdx.x) >> 5;
  int lane = threadIdx.x & 31;
  if (w >= NN) return;
  const float* row = adj + (size_t)w * NN;
  int cur = rowptr[w];
  for (int j0 = 0; j0 < NN; j0 += 32) {
    float v = row[j0 + lane];
    unsigned mask = __ballot_sync(0xffffffffu, v > 0.0f);
    if (v > 0.0f) {
      int pos = __popc(mask & ((1u << lane) - 1u));
      cols[cur + pos] = j0 + lane;
    }
    cur += __popc(mask);
  }
}

// ---------------- split conversions ----------------
__global__ void split_f32(const float* __restrict__ in, __nv_bfloat16* __restrict__ oh,
                          __nv_bfloat16* __restrict__ ol, long long n) {
  long long i = (long long)blockIdx.x * blockDim.x + threadIdx.x;
  if (i >= n) return;
  float x = in[i];
  __nv_bfloat16 h = __float2bfloat16(x);
  oh[i] = h;
  ol[i] = __float2bfloat16(x - __bfloat162float(h));
}

// W [b][Kd,Nd] row-major -> out [b][Nd,Kd] (K-major, for MMA B operand)
__global__ void split_tr(const float* __restrict__ W, __nv_bfloat16* __restrict__ oh,
                         __nv_bfloat16* __restrict__ ol, int Kd, int Nd, int nb) {
  long long tot = (long long)nb * Kd * Nd;
  long long i = (long long)blockIdx.x * blockDim.x + threadIdx.x;
  if (i >= tot) return;
  long long per = (long long)Kd * Nd;
  int b = (int)(i / per);
  int r = (int)(i % per);
  int n = r / Kd, k = r % Kd;
  float x = W[(long long)b * per + (long long)k * Nd + n];
  __nv_bfloat16 h = __float2bfloat16(x);
  oh[i] = h;
  ol[i] = __float2bfloat16(x - __bfloat162float(h));
}

// ---------------- HMMA split-bf16 GEMM ----------------
// C[m,n] = sum_k A[m,k]*B[n,k], A=Ah+Al, B=Bh+Bl (3-pass, drop Al*Bl).
// CTA tile 128x128, 8 warps (2x4 grid of 64x32 warptiles), K-chunks of 64,
// cp.async double buffer. Requires M%128==0, Nn%128==0, (K/kChunks)%64==0.
#define TRS 72                       // padded row stride (bf16 elems) = 144B
#define TILE_B (128 * TRS * 2)       // 18432B per tile
#define CHUNK_B (4 * TILE_B)         // Ah,Al,Bh,Bl
#define GSM_TOTAL (2 * CHUNK_B)      // 147456B

__global__ void __launch_bounds__(256) gemm_mma(
    const __nv_bfloat16* __restrict__ Ah, const __nv_bfloat16* __restrict__ Al,
    const __nv_bfloat16* __restrict__ Bh, const __nv_bfloat16* __restrict__ Bl,
    float* __restrict__ C,
    int Nn, int K,
    long long strideB, long long strideC,
    int kChunks, long long chunkStride) {
  extern __shared__ char smem[];
  uint32_t sb = smem_u32(smem);
  int tx = threadIdx.x;
  int wid = tx >> 5, lane = tx & 31;

  int z = blockIdx.z;
  int batch = z / kChunks;
  int chunk = z % kChunks;
  int Kc = K / kChunks;
  int NC = Kc >> 6;
  int kbeg = chunk * Kc;
  int row0 = blockIdx.y << 7, col0 = blockIdx.x << 7;

  const __nv_bfloat16* srcs[4];
  srcs[0] = Ah + (size_t)row0 * K;
  srcs[1] = Al + (size_t)row0 * K;
  srcs[2] = Bh + (size_t)batch * strideB + (size_t)col0 * K;
  srcs[3] = Bl + (size_t)batch * strideB + (size_t)col0 * K;

  float acc[4][4][4];
#pragma unroll
  for (int a = 0; a < 4; a++)
#pragma unroll
    for (int b = 0; b < 4; b++)
#pragma unroll
      for (int q = 0; q < 4; q++) acc[a][b][q] = 0.0f;

  // warp tiling
  int wr = wid >> 2, wc = wid & 3;
  // ldmatrix lane-derived offsets
  int a_row_off = (lane & 7) + ((lane >> 3) & 1) * 8;   // within 16
  int a_col_off = (lane >> 4) * 8;                      // 0 or 8
  int b_row_off = lane & 7;                             // within 8 (x2 uses lanes 0-15)
  int b_col_off = ((lane >> 3) & 1) * 8;

#define LOAD_CHUNK(c, buf)                                                      \
  do {                                                                          \
    int k0 = kbeg + ((c) << 6);                                                 \
    uint32_t dst0 = sb + (buf) * CHUNK_B;                                       \
    _Pragma("unroll")                                                           \
    for (int t4 = 0; t4 < 4; t4++) {                                            \
      const char* srcb = (const char*)(srcs[t4] + k0);                          \
      uint32_t dt = dst0 + t4 * TILE_B;                                         \
      _Pragma("unroll")                                                         \
      for (int it = 0; it < 4; it++) {                                          \
        int lin = it * 256 + tx;                                                \
        int row = lin >> 3, seg = lin & 7;                                      \
        CP_ASYNC16(dt + row * (TRS * 2) + seg * 16,                             \
                   srcb + (size_t)row * K * 2 + seg * 16);                      \
      }                                                                         \
    }                                                                           \
    CP_COMMIT();                                                                \
  } while (0)

  LOAD_CHUNK(0, 0);
  if (NC > 1) { LOAD_CHUNK(1, 1); CP_WAIT1(); } else { CP_WAIT0(); }
  __syncthreads();

  for (int c = 0; c < NC; c++) {
    int buf = c & 1;
    uint32_t base = sb + buf * CHUNK_B;
    uint32_t tAh = base, tAl = base + TILE_B, tBh = base + 2 * TILE_B, tBl = base + 3 * TILE_B;
#pragma unroll
    for (int ks = 0; ks < 4; ks++) {
      int kb = ks << 4;
      uint32_t acol2 = (uint32_t)(kb + a_col_off) * 2;
      uint32_t bcol2 = (uint32_t)(kb + b_col_off) * 2;
      uint32_t ah[4][4], al[4][4], bh[4][2], bl[4][2];
#pragma unroll
      for (int mf = 0; mf < 4; mf++) {
        uint32_t ad = tAh + (uint32_t)(wr * 64 + mf * 16 + a_row_off) * (TRS * 2) + acol2;
        LDMX4(ah[mf][0], ah[mf][1], ah[mf][2], ah[mf][3], ad);
      }
#pragma unroll
      for (int nf = 0; nf < 4; nf++) {
        uint32_t bd = tBh + (uint32_t)(wc * 32 + nf * 8 + b_row_off) * (TRS * 2) + bcol2;
        LDMX2(bh[nf][0], bh[nf][1], bd);
      }
#pragma unroll
      for (int mf = 0; mf < 4; mf++)
#pragma unroll
        for (int nf = 0; nf < 4; nf++) MMA16816(acc[mf][nf], ah[mf], bh[nf]);
#pragma unroll
      for (int nf = 0; nf < 4; nf++) {
        uint32_t bd = tBl + (uint32_t)(wc * 32 + nf * 8 + b_row_off) * (TRS * 2) + bcol2;
        LDMX2(bl[nf][0], bl[nf][1], bd);
      }
#pragma unroll
      for (int mf = 0; mf < 4; mf++)
#pragma unroll
        for (int nf = 0; nf < 4; nf++) MMA16816(acc[mf][nf], ah[mf], bl[nf]);
#pragma unroll
      for (int mf = 0; mf < 4; mf++) {
        uint32_t ad = tAl + (uint32_t)(wr * 64 + mf * 16 + a_row_off) * (TRS * 2) + acol2;
        LDMX4(al[mf][0], al[mf][1], al[mf][2], al[mf][3], ad);
      }
#pragma unroll
      for (int mf = 0; mf < 4; mf++)
#pragma unroll
        for (int nf = 0; nf < 4; nf++) MMA16816(acc[mf][nf], al[mf], bh[nf]);
    }
    __syncthreads();
    bool more = (c + 2) < NC;
    if (more) LOAD_CHUNK(c + 2, buf);
    if (c + 1 < NC) {
      if (more) CP_WAIT1(); else CP_WAIT0();
      __syncthreads();
    }
  }

  // epilogue
  float* Cc = C + (size_t)batch * strideC + (size_t)chunk * chunkStride;
  int mbase = row0 + wr * 64;
  int nbase = col0 + wc * 32;
  int rl = lane >> 2, cl = (lane & 3) * 2;
#pragma unroll
  for (int mf = 0; mf < 4; mf++)
#pragma unroll
    for (int nf = 0; nf < 4; nf++) {
      int r = mbase + mf * 16 + rl;
      int cc = nbase + nf * 8 + cl;
      float2 lo = make_float2(acc[mf][nf][0], acc[mf][nf][1]);
      float2 hi = make_float2(acc[mf][nf][2], acc[mf][nf][3]);
      *(float2*)(Cc + (size_t)r * Nn + cc) = lo;
      *(float2*)(Cc + (size_t)(r + 8) * Nn + cc) = hi;
    }
}

// ---------------- split-K reduce (fixed order -> deterministic) ----------------
__global__ void reduce8(const float* __restrict__ part, float* __restrict__ out,
                        long long n, long long stride) {
  long long i = (long long)blockIdx.x * blockDim.x + threadIdx.x;
  if (i >= n) return;
  float s = part[i];
#pragma unroll
  for (int c = 1; c < 8; c++) s += part[i + c * stride];
  out[i] = s;
}

// ---------------- s1/s2: per-row dual dot with attention vector ----------------
__global__ void rowdot2(const float* __restrict__ feat, const float* __restrict__ a,
                        float* __restrict__ o1, float* __restrict__ o2, int D) {
  int h = blockIdx.y;
  int w = blockIdx.x * (blockDim.x >> 5) + (threadIdx.x >> 5);
  int lane = threadIdx.x & 31;
  if (w >= NN) return;
  const float* f = feat + ((size_t)h * NN + w) * D;
  const float* a1 = a + (size_t)h * 2 * D;
  const float* a2 = a1 + D;
  float d1 = 0.0f, d2 = 0.0f;
  for (int d = lane; d < D; d += 32) {
    float v = f[d];
    d1 += v * a1[d];
    d2 += v * a2[d];
  }
  for (int o = 16; o; o >>= 1) {
    d1 += __shfl_down_sync(0xffffffffu, d1, o);
    d2 += __shfl_down_sync(0xffffffffu, d2, o);
  }
  if (lane == 0) {
    o1[(size_t)h * NN + w] = d1;
    o2[(size_t)h * NN + w] = d2;
  }
}

// ---------------- sparse masked softmax attention + aggregate + elu ----------------
__global__ void __launch_bounds__(128) attn_agg(
    const int* __restrict__ rowptr, const int* __restrict__ cols,
    const float* __restrict__ s1, const float* __restrict__ s2,
    const float* __restrict__ feat, float* __restrict__ out,
    int D, long long outRowStride) {
  int i = blockIdx.x, h = blockIdx.y;
  int t = threadIdx.x;
  __shared__ float red[128];
  __shared__ float shw[128];
  __shared__ int shc[128];
  float s1i = s1[(size_t)h * NN + i];
  const float* s2h = s2 + (size_t)h * NN;
  const float* fh = feat + (size_t)h * NN * D;
  int start = rowptr[i], end = rowptr[i + 1];

  float m = -1e30f;
  for (int e = start + t; e < end; e += 128) {
    float z = s1i + s2h[cols[e]];
    z = z > 0.0f ? z : 0.2f * z;
    m = fmaxf(m, z);
  }
  red[t] = m;
  __syncthreads();
  for (int s = 64; s > 0; s >>= 1) {
    if (t < s) red[t] = fmaxf(red[t], red[t + s]);
    __syncthreads();
  }
  m = red[0];

  int dper = D >> 7;
  float acc[4] = {0.0f, 0.0f, 0.0f, 0.0f};
  float dsum = 0.0f;
  for (int c0 = start; c0 < end; c0 += 128) {
    int len = min(128, end - c0);
    __syncthreads();
    if (t < len) {
      int j = cols[c0 + t];
      float z = s1i + s2h[j];
      z = z > 0.0f ? z : 0.2f * z;
      float w = expf(z - m);
      shw[t] = w;
      shc[t] = j;
      dsum += w;
    }
    __syncthreads();
    for (int jj = 0; jj < len; jj++) {
      float w = shw[jj];
      const float* fj = fh + (size_t)shc[jj] * D;
#pragma unroll
      for (int q = 0; q < 4; q++)
        if (q < dper) acc[q] += w * fj[t + (q << 7)];
    }
  }
  __syncthreads();
  red[t] = dsum;
  __syncthreads();
  for (int s = 64; s > 0; s >>= 1) {
    if (t < s) red[t] += red[t + s];
    __syncthreads();
  }
  float inv = 1.0f / red[0];
  float* orow = out + (size_t)i * outRowStride + (size_t)h * D;
  for (int q = 0; q < dper; q++) {
    float v = acc[q] * inv;
    orow[t + (q << 7)] = v > 0.0f ? v : expm1f(v);
  }
}

// ---------------- orchestration ----------------
extern "C" void kernel_launch(void* const* d_in, const int* in_sizes, int n_in,
                              void* d_out, int out_size) {
  (void)in_sizes; (void)n_in; (void)out_size;
  const float* x = (const float*)d_in[0];
  const float* adj = (const float*)d_in[1];

  float *p_h, *p_hcat, *p_ho, *p_part, *p_xA, *p_xB, *p_s1, *p_s2, *p_t1, *p_t2;
  int *p_deg, *p_rowptr, *p_cols;
  __nv_bfloat16 *p_aH, *p_aL, *p_bH, *p_bL;
  cudaGetSymbolAddress((void**)&p_h, g_h);
  cudaGetSymbolAddress((void**)&p_hcat, g_hcat);
  cudaGetSymbolAddress((void**)&p_ho, g_ho);
  cudaGetSymbolAddress((void**)&p_part, g_part);
  cudaGetSymbolAddress((void**)&p_xA, g_xA);
  cudaGetSymbolAddress((void**)&p_xB, g_xB);
  cudaGetSymbolAddress((void**)&p_s1, g_s1);
  cudaGetSymbolAddress((void**)&p_s2, g_s2);
  cudaGetSymbolAddress((void**)&p_t1, g_t1);
  cudaGetSymbolAddress((void**)&p_t2, g_t2);
  cudaGetSymbolAddress((void**)&p_deg, g_deg);
  cudaGetSymbolAddress((void**)&p_rowptr, g_rowptr);
  cudaGetSymbolAddress((void**)&p_cols, g_cols);
  cudaGetSymbolAddress((void**)&p_aH, g_aH);
  cudaGetSymbolAddress((void**)&p_aL, g_aL);
  cudaGetSymbolAddress((void**)&p_bH, g_bH);
  cudaGetSymbolAddress((void**)&p_bL, g_bL);

  cudaFuncSetAttribute(gemm_mma, cudaFuncAttributeMaxDynamicSharedMemorySize, GSM_TOTAL);

  // build CSR of fixed adjacency (cheap; deterministic ordering)
  deg_kernel<<<256, 256>>>(adj, p_deg);
  scan_kernel<<<1, 1024>>>(p_deg, p_rowptr);
  fill_kernel<<<256, 256>>>(adj, p_rowptr, p_cols);

  const int FIN[6]  = {256, 128, 256, 384, 256, 128};
  const int HID[6]  = {128, 256, 512, 512, 256, 128};
  const int FOUT[6] = {128, 256, 384, 256, 128, 256};

  const float* cur = x;
  for (int L = 0; L < 6; L++) {
    const float* Wh = (const float*)d_in[2 + 4 * L + 0];
    const float* ah = (const float*)d_in[2 + 4 * L + 1];
    const float* Wo = (const float*)d_in[2 + 4 * L + 2];
    const float* ao = (const float*)d_in[2 + 4 * L + 3];
    int fin = FIN[L], hid = HID[L], fout = FOUT[L];

    // split features and per-head weights (transposed to [hid,fin])
    {
      long long n = (long long)NN * fin;
      split_f32<<<(unsigned)((n + 255) / 256), 256>>>(cur, p_aH, p_aL, n);
      long long wtot = (long long)NH * fin * hid;
      split_tr<<<(unsigned)((wtot + 255) / 256), 256>>>(Wh, p_bH, p_bL, fin, hid, NH);
    }
    // h[head] = cur @ Wh[head]  -> [H, N, hid]  (HMMA, batched over heads)
    gemm_mma<<<dim3(hid / 128, NN / 128, NH), 256, GSM_TOTAL>>>(
        p_aH, p_aL, p_bH, p_bL, p_h, hid, fin,
        (long long)fin * hid, (long long)NN * hid, 1, 0);
    // s1/s2 per head
    rowdot2<<<dim3(NN / 8, NH), 256>>>(p_h, ah, p_s1, p_s2, hid);
    // sparse attention aggregate + elu -> hcat [N, H*hid]
    attn_agg<<<dim3(NN, NH), 128>>>(p_rowptr, p_cols, p_s1, p_s2, p_h, p_hcat,
                                    hid, (long long)NH * hid);
    // split hcat and Wo (transposed to [fout, 8*hid])
    {
      long long n = (long long)NN * NH * hid;
      split_f32<<<(unsigned)((n + 255) / 256), 256>>>(p_hcat, p_aH, p_aL, n);
      long long wtot = (long long)NH * hid * fout;
      split_tr<<<(unsigned)((wtot + 255) / 256), 256>>>(Wo, p_bH, p_bL, NH * hid, fout, 1);
    }
    // ho = hcat @ Wo -> [N, fout]  via split-K 8 (deterministic reduce)
    gemm_mma<<<dim3(fout / 128, NN / 128, 8), 256, GSM_TOTAL>>>(
        p_aH, p_aL, p_bH, p_bL, p_part, fout, NH * hid,
        0, 0, 8, (long long)NN * fout);
    {
      long long n = (long long)NN * fout;
      reduce8<<<(unsigned)((n + 255) / 256), 256>>>(p_part, p_ho, n,
                                                    (long long)NN * fout);
    }
    // output-head scores
    rowdot2<<<dim3(NN / 8, 1), 256>>>(p_ho, ao, p_t1, p_t2, fout);
    // output sparse attention + elu -> next features (or final output)
    float* dst = (L == 5) ? (float*)d_out : ((L & 1) ? p_xB : p_xA);
    attn_agg<<<dim3(NN, 1), 128>>>(p_rowptr, p_cols, p_t1, p_t2, p_ho, dst,
                                   fout, (long long)fout);
    cur = dst;
  }
}

// round 11
// speedup vs baseline: 1.5356x; 1.0603x over previous
#include <cuda_runtime.h>
#include <cuda_bf16.h>
#include <math.h>
#include <stdint.h>

#define NN 2048
#define NH 8

// ---------------- static scratch (allocation-free rule) ----------------
__device__ float g_h[(size_t)NH * NN * 512];        // per-head hidden  [H,N,hid<=512]
__device__ float g_ho[(size_t)NN * 512];            // [N, fout<=384]
__device__ float g_part[(size_t)8 * NN * 384];      // split-K partials (8 chunks)
__device__ float g_s1[NH * NN];
__device__ float g_s2[NH * NN];
__device__ float g_t1[NN];
__device__ float g_t2[NN];
__device__ int   g_deg[NN];
__device__ int   g_rowptr[NN + 1];
__device__ int   g_cols[(size_t)NN * NN];           // worst-case capacity
// split-bf16 operands (16B-aligned for cp.async)
__device__ __align__(256) __nv_bfloat16 g_aH[(size_t)NN * 4096];
__device__ __align__(256) __nv_bfloat16 g_aL[(size_t)NN * 4096];
__device__ __align__(256) __nv_bfloat16 g_bH[2097152];
__device__ __align__(256) __nv_bfloat16 g_bL[2097152];

// ---------------- PTX helpers (sm_80-class only; compiles at compute_103) ---
__device__ __forceinline__ uint32_t smem_u32(const void* p) {
  uint32_t a;
  asm("{ .reg .u64 t; cvta.to.shared.u64 t, %1; cvt.u32.u64 %0, t; }" : "=r"(a) : "l"(p));
  return a;
}
#define CP_ASYNC16(d, s) \
  asm volatile("cp.async.cg.shared.global [%0], [%1], 16;" :: "r"(d), "l"(s) : "memory")
#define CP_COMMIT() asm volatile("cp.async.commit_group;" ::: "memory")
#define CP_WAIT0() asm volatile("cp.async.wait_group 0;" ::: "memory")
#define CP_WAIT1() asm volatile("cp.async.wait_group 1;" ::: "memory")
#define LDMX4(r0, r1, r2, r3, a) \
  asm volatile("ldmatrix.sync.aligned.m8n8.x4.shared.b16 {%0,%1,%2,%3}, [%4];" \
               : "=r"(r0), "=r"(r1), "=r"(r2), "=r"(r3) : "r"(a))
#define LDMX2(r0, r1, a) \
  asm volatile("ldmatrix.sync.aligned.m8n8.x2.shared.b16 {%0,%1}, [%2];" \
               : "=r"(r0), "=r"(r1) : "r"(a))
#define MMA16816(c, a, b) \
  asm volatile( \
      "mma.sync.aligned.m16n8k16.row.col.f32.bf16.bf16.f32 " \
      "{%0,%1,%2,%3}, {%4,%5,%6,%7}, {%8,%9}, {%0,%1,%2,%3};" \
      : "+f"((c)[0]), "+f"((c)[1]), "+f"((c)[2]), "+f"((c)[3]) \
      : "r"((a)[0]), "r"((a)[1]), "r"((a)[2]), "r"((a)[3]), "r"((b)[0]), "r"((b)[1]))

// ---------------- CSR build (deterministic, no atomics) ----------------
__global__ void deg_kernel(const float* __restrict__ adj, int* __restrict__ deg) {
  int w = (blockIdx.x * blockDim.x + threadIdx.x) >> 5;
  int lane = threadIdx.x & 31;
  if (w >= NN) return;
  const float* row = adj + (size_t)w * NN;
  int c = 0;
  for (int j = lane; j < NN; j += 32) c += (row[j] > 0.0f);
  for (int o = 16; o; o >>= 1) c += __shfl_down_sync(0xffffffffu, c, o);
  if (lane == 0) deg[w] = c;
}

__global__ void scan_kernel(const int* __restrict__ deg, int* __restrict__ rowptr) {
  __shared__ int p[1024];
  int t = threadIdx.x;
  int a = deg[2 * t];
  int b = deg[2 * t + 1];
  p[t] = a + b;
  __syncthreads();
  for (int off = 1; off < 1024; off <<= 1) {
    int v = (t >= off) ? p[t - off] : 0;
    __syncthreads();
    p[t] += v;
    __syncthreads();
  }
  int excl = (t == 0) ? 0 : p[t - 1];
  rowptr[2 * t] = excl;
  rowptr[2 * t + 1] = excl + a;
  if (t == 1023) rowptr[NN] = p[1023];
}

__global__ void fill_kernel(const float* __restrict__ adj,
                            const int* __restrict__ rowptr,
                            int* __restrict__ cols) {
  int w = (blockIdx.x * blockDim.x + threadIdx.x) >> 5;
  int lane = threadIdx.x & 31;
  if (w >= NN) return;
  const float* row = adj + (size_t)w * NN;
  int cur = rowptr[w];
  for (int j0 = 0; j0 < NN; j0 += 32) {
    float v = row[j0 + lane];
    unsigned mask = __ballot_sync(0xffffffffu, v > 0.0f);
    if (v > 0.0f) {
      int pos = __popc(mask & ((1u << lane) - 1u));
      cols[cur + pos] = j0 + lane;
    }
    cur += __popc(mask);
  }
}

// ---------------- split conversions ----------------
__global__ void split_f32(const float* __restrict__ in, __nv_bfloat16* __restrict__ oh,
                          __nv_bfloat16* __restrict__ ol, long long n) {
  long long i = (long long)blockIdx.x * blockDim.x + threadIdx.x;
  if (i >= n) return;
  float x = in[i];
  __nv_bfloat16 h = __float2bfloat16(x);
  oh[i] = h;
  ol[i] = __float2bfloat16(x - __bfloat162float(h));
}

// W [b][Kd,Nd] row-major -> out [b][Nd,Kd]  (coalesced tiled transpose + split)
// grid (Nd/32, Kd/32, nb), block (32, 8). Kd, Nd multiples of 32.
__global__ void split_tr(const float* __restrict__ W, __nv_bfloat16* __restrict__ oh,
                         __nv_bfloat16* __restrict__ ol, int Kd, int Nd) {
  __shared__ float tile[32][33];
  int b = blockIdx.z;
  int n0 = blockIdx.x << 5, k0 = blockIdx.y << 5;
  const float* Wb = W + (size_t)b * Kd * Nd;
#pragma unroll
  for (int r = threadIdx.y; r < 32; r += 8)
    tile[r][threadIdx.x] = Wb[(size_t)(k0 + r) * Nd + n0 + threadIdx.x];
  __syncthreads();
  size_t obase = (size_t)b * Kd * Nd;
#pragma unroll
  for (int r = threadIdx.y; r < 32; r += 8) {
    float x = tile[threadIdx.x][r];
    __nv_bfloat16 h = __float2bfloat16(x);
    size_t idx = obase + (size_t)(n0 + r) * Kd + k0 + threadIdx.x;
    oh[idx] = h;
    ol[idx] = __float2bfloat16(x - __bfloat162float(h));
  }
}

// ---------------- HMMA split-bf16 GEMM ----------------
// C[m,n] = sum_k A[m,k]*B[n,k], A=Ah+Al, B=Bh+Bl (3-pass, drop Al*Bl).
// CTA tile 128x128, 8 warps (2x4 grid of 64x32 warptiles), K-chunks of 64,
// cp.async double buffer. Requires M%128==0, Nn%128==0, (K/kChunks)%64==0.
#define TRS 72                       // padded row stride (bf16 elems) = 144B
#define TILE_B (128 * TRS * 2)       // 18432B per tile
#define CHUNK_B (4 * TILE_B)         // Ah,Al,Bh,Bl
#define GSM_TOTAL (2 * CHUNK_B)      // 147456B

__global__ void __launch_bounds__(256) gemm_mma(
    const __nv_bfloat16* __restrict__ Ah, const __nv_bfloat16* __restrict__ Al,
    const __nv_bfloat16* __restrict__ Bh, const __nv_bfloat16* __restrict__ Bl,
    float* __restrict__ C,
    int Nn, int K,
    long long strideB, long long strideC,
    int kChunks, long long chunkStride) {
  extern __shared__ char smem[];
  uint32_t sb = smem_u32(smem);
  int tx = threadIdx.x;
  int wid = tx >> 5, lane = tx & 31;

  int z = blockIdx.z;
  int batch = z / kChunks;
  int chunk = z % kChunks;
  int Kc = K / kChunks;
  int NC = Kc >> 6;
  int kbeg = chunk * Kc;
  int row0 = blockIdx.y << 7, col0 = blockIdx.x << 7;

  const __nv_bfloat16* srcs[4];
  srcs[0] = Ah + (size_t)row0 * K;
  srcs[1] = Al + (size_t)row0 * K;
  srcs[2] = Bh + (size_t)batch * strideB + (size_t)col0 * K;
  srcs[3] = Bl + (size_t)batch * strideB + (size_t)col0 * K;

  float acc[4][4][4];
#pragma unroll
  for (int a = 0; a < 4; a++)
#pragma unroll
    for (int b = 0; b < 4; b++)
#pragma unroll
      for (int q = 0; q < 4; q++) acc[a][b][q] = 0.0f;

  // warp tiling
  int wr = wid >> 2, wc = wid & 3;
  // ldmatrix lane-derived offsets
  int a_row_off = (lane & 7) + ((lane >> 3) & 1) * 8;   // within 16
  int a_col_off = (lane >> 4) * 8;                      // 0 or 8
  int b_row_off = lane & 7;                             // within 8 (x2 uses lanes 0-15)
  int b_col_off = ((lane >> 3) & 1) * 8;

#define LOAD_CHUNK(c, buf)                                                      \
  do {                                                                          \
    int k0 = kbeg + ((c) << 6);                                                 \
    uint32_t dst0 = sb + (buf) * CHUNK_B;                                       \
    _Pragma("unroll")                                                           \
    for (int t4 = 0; t4 < 4; t4++) {                                            \
      const char* srcb = (const char*)(srcs[t4] + k0);                          \
      uint32_t dt = dst0 + t4 * TILE_B;                                         \
      _Pragma("unroll")                                                         \
      for (int it = 0; it < 4; it++) {                                          \
        int lin = it * 256 + tx;                                                \
        int row = lin >> 3, seg = lin & 7;                                      \
        CP_ASYNC16(dt + row * (TRS * 2) + seg * 16,                             \
                   srcb + (size_t)row * K * 2 + seg * 16);                      \
      }                                                                         \
    }                                                                           \
    CP_COMMIT();                                                                \
  } while (0)

  LOAD_CHUNK(0, 0);
  if (NC > 1) { LOAD_CHUNK(1, 1); CP_WAIT1(); } else { CP_WAIT0(); }
  __syncthreads();

  for (int c = 0; c < NC; c++) {
    int buf = c & 1;
    uint32_t base = sb + buf * CHUNK_B;
    uint32_t tAh = base, tAl = base + TILE_B, tBh = base + 2 * TILE_B, tBl = base + 3 * TILE_B;
#pragma unroll
    for (int ks = 0; ks < 4; ks++) {
      int kb = ks << 4;
      uint32_t acol2 = (uint32_t)(kb + a_col_off) * 2;
      uint32_t bcol2 = (uint32_t)(kb + b_col_off) * 2;
      uint32_t ah[4][4], al[4][4], bh[4][2], bl[4][2];
#pragma unroll
      for (int mf = 0; mf < 4; mf++) {
        uint32_t ad = tAh + (uint32_t)(wr * 64 + mf * 16 + a_row_off) * (TRS * 2) + acol2;
        LDMX4(ah[mf][0], ah[mf][1], ah[mf][2], ah[mf][3], ad);
      }
#pragma unroll
      for (int nf = 0; nf < 4; nf++) {
        uint32_t bd = tBh + (uint32_t)(wc * 32 + nf * 8 + b_row_off) * (TRS * 2) + bcol2;
        LDMX2(bh[nf][0], bh[nf][1], bd);
      }
#pragma unroll
      for (int mf = 0; mf < 4; mf++)
#pragma unroll
        for (int nf = 0; nf < 4; nf++) MMA16816(acc[mf][nf], ah[mf], bh[nf]);
#pragma unroll
      for (int nf = 0; nf < 4; nf++) {
        uint32_t bd = tBl + (uint32_t)(wc * 32 + nf * 8 + b_row_off) * (TRS * 2) + bcol2;
        LDMX2(bl[nf][0], bl[nf][1], bd);
      }
#pragma unroll
      for (int mf = 0; mf < 4; mf++)
#pragma unroll
        for (int nf = 0; nf < 4; nf++) MMA16816(acc[mf][nf], ah[mf], bl[nf]);
#pragma unroll
      for (int mf = 0; mf < 4; mf++) {
        uint32_t ad = tAl + (uint32_t)(wr * 64 + mf * 16 + a_row_off) * (TRS * 2) + acol2;
        LDMX4(al[mf][0], al[mf][1], al[mf][2], al[mf][3], ad);
      }
#pragma unroll
      for (int mf = 0; mf < 4; mf++)
#pragma unroll
        for (int nf = 0; nf < 4; nf++) MMA16816(acc[mf][nf], al[mf], bh[nf]);
    }
    __syncthreads();
    bool more = (c + 2) < NC;
    if (more) LOAD_CHUNK(c + 2, buf);
    if (c + 1 < NC) {
      if (more) CP_WAIT1(); else CP_WAIT0();
      __syncthreads();
    }
  }

  // epilogue
  float* Cc = C + (size_t)batch * strideC + (size_t)chunk * chunkStride;
  int mbase = row0 + wr * 64;
  int nbase = col0 + wc * 32;
  int rl = lane >> 2, cl = (lane & 3) * 2;
#pragma unroll
  for (int mf = 0; mf < 4; mf++)
#pragma unroll
    for (int nf = 0; nf < 4; nf++) {
      int r = mbase + mf * 16 + rl;
      int cc = nbase + nf * 8 + cl;
      float2 lo = make_float2(acc[mf][nf][0], acc[mf][nf][1]);
      float2 hi = make_float2(acc[mf][nf][2], acc[mf][nf][3]);
      *(float2*)(Cc + (size_t)r * Nn + cc) = lo;
      *(float2*)(Cc + (size_t)(r + 8) * Nn + cc) = hi;
    }
}

// ---------------- split-K reduce (fixed order -> deterministic) ----------------
__global__ void reduce8(const float* __restrict__ part, float* __restrict__ out,
                        long long n, long long stride) {
  long long i = (long long)blockIdx.x * blockDim.x + threadIdx.x;
  if (i >= n) return;
  float s = part[i];
#pragma unroll
  for (int c = 1; c < 8; c++) s += part[i + c * stride];
  out[i] = s;
}

// ---------------- s1/s2: per-row dual dot with attention vector ----------------
__global__ void rowdot2(const float* __restrict__ feat, const float* __restrict__ a,
                        float* __restrict__ o1, float* __restrict__ o2, int D) {
  int h = blockIdx.y;
  int w = blockIdx.x * (blockDim.x >> 5) + (threadIdx.x >> 5);
  int lane = threadIdx.x & 31;
  if (w >= NN) return;
  const float* f = feat + ((size_t)h * NN + w) * D;
  const float* a1 = a + (size_t)h * 2 * D;
  const float* a2 = a1 + D;
  float d1 = 0.0f, d2 = 0.0f;
  for (int d = lane; d < D; d += 32) {
    float v = f[d];
    d1 += v * a1[d];
    d2 += v * a2[d];
  }
  for (int o = 16; o; o >>= 1) {
    d1 += __shfl_down_sync(0xffffffffu, d1, o);
    d2 += __shfl_down_sync(0xffffffffu, d2, o);
  }
  if (lane == 0) {
    o1[(size_t)h * NN + w] = d1;
    o2[(size_t)h * NN + w] = d2;
  }
}

// ---------------- sparse masked softmax attention + aggregate + elu ----------------
// Writes fp32 (outF) and/or split-bf16 (outH/outL) per launch flags.
__global__ void __launch_bounds__(128) attn_agg(
    const int* __restrict__ rowptr, const int* __restrict__ cols,
    const float* __restrict__ s1, const float* __restrict__ s2,
    const float* __restrict__ feat,
    float* __restrict__ outF,
    __nv_bfloat16* __restrict__ outH, __nv_bfloat16* __restrict__ outL,
    int D, long long outRowStride) {
  int i = blockIdx.x, h = blockIdx.y;
  int t = threadIdx.x;
  __shared__ float red[128];
  __shared__ float shw[128];
  __shared__ int shc[128];
  float s1i = s1[(size_t)h * NN + i];
  const float* s2h = s2 + (size_t)h * NN;
  const float* fh = feat + (size_t)h * NN * D;
  int start = rowptr[i], end = rowptr[i + 1];

  float m = -1e30f;
  for (int e = start + t; e < end; e += 128) {
    float z = s1i + s2h[cols[e]];
    z = z > 0.0f ? z : 0.2f * z;
    m = fmaxf(m, z);
  }
  red[t] = m;
  __syncthreads();
  for (int s = 64; s > 0; s >>= 1) {
    if (t < s) red[t] = fmaxf(red[t], red[t + s]);
    __syncthreads();
  }
  m = red[0];

  int dper = D >> 7;
  float acc[4] = {0.0f, 0.0f, 0.0f, 0.0f};
  float dsum = 0.0f;
  for (int c0 = start; c0 < end; c0 += 128) {
    int len = min(128, end - c0);
    __syncthreads();
    if (t < len) {
      int j = cols[c0 + t];
      float z = s1i + s2h[j];
      z = z > 0.0f ? z : 0.2f * z;
      float w = expf(z - m);
      shw[t] = w;
      shc[t] = j;
      dsum += w;
    }
    __syncthreads();
    for (int jj = 0; jj < len; jj++) {
      float w = shw[jj];
      const float* fj = fh + (size_t)shc[jj] * D;
#pragma unroll
      for (int q = 0; q < 4; q++)
        if (q < dper) acc[q] += w * fj[t + (q << 7)];
    }
  }
  __syncthreads();
  red[t] = dsum;
  __syncthreads();
  for (int s = 64; s > 0; s >>= 1) {
    if (t < s) red[t] += red[t + s];
    __syncthreads();
  }
  float inv = 1.0f / red[0];
  long long obase = (size_t)i * outRowStride + (size_t)h * D;
  for (int q = 0; q < dper; q++) {
    float v = acc[q] * inv;
    v = v > 0.0f ? v : expm1f(v);  // elu
    long long idx = obase + t + (q << 7);
    if (outF) outF[idx] = v;
    if (outH) {
      __nv_bfloat16 hv = __float2bfloat16(v);
      outH[idx] = hv;
      outL[idx] = __float2bfloat16(v - __bfloat162float(hv));
    }
  }
}

// ---------------- orchestration ----------------
extern "C" void kernel_launch(void* const* d_in, const int* in_sizes, int n_in,
                              void* d_out, int out_size) {
  (void)in_sizes; (void)n_in; (void)out_size;
  const float* x = (const float*)d_in[0];
  const float* adj = (const float*)d_in[1];

  float *p_h, *p_ho, *p_part, *p_s1, *p_s2, *p_t1, *p_t2;
  int *p_deg, *p_rowptr, *p_cols;
  __nv_bfloat16 *p_aH, *p_aL, *p_bH, *p_bL;
  cudaGetSymbolAddress((void**)&p_h, g_h);
  cudaGetSymbolAddress((void**)&p_ho, g_ho);
  cudaGetSymbolAddress((void**)&p_part, g_part);
  cudaGetSymbolAddress((void**)&p_s1, g_s1);
  cudaGetSymbolAddress((void**)&p_s2, g_s2);
  cudaGetSymbolAddress((void**)&p_t1, g_t1);
  cudaGetSymbolAddress((void**)&p_t2, g_t2);
  cudaGetSymbolAddress((void**)&p_deg, g_deg);
  cudaGetSymbolAddress((void**)&p_rowptr, g_rowptr);
  cudaGetSymbolAddress((void**)&p_cols, g_cols);
  cudaGetSymbolAddress((void**)&p_aH, g_aH);
  cudaGetSymbolAddress((void**)&p_aL, g_aL);
  cudaGetSymbolAddress((void**)&p_bH, g_bH);
  cudaGetSymbolAddress((void**)&p_bL, g_bL);

  cudaFuncSetAttribute(gemm_mma, cudaFuncAttributeMaxDynamicSharedMemorySize, GSM_TOTAL);

  // build CSR of fixed adjacency (cheap; deterministic ordering)
  deg_kernel<<<256, 256>>>(adj, p_deg);
  scan_kernel<<<1, 1024>>>(p_deg, p_rowptr);
  fill_kernel<<<256, 256>>>(adj, p_rowptr, p_cols);

  const int FIN[6]  = {256, 128, 256, 384, 256, 128};
  const int HID[6]  = {128, 256, 512, 512, 256, 128};
  const int FOUT[6] = {128, 256, 384, 256, 128, 256};

  // layer-0 features split (later layers fused into attn_agg epilogue)
  {
    long long n = (long long)NN * 256;
    split_f32<<<(unsigned)((n + 255) / 256), 256>>>(x, p_aH, p_aL, n);
  }

  for (int L = 0; L < 6; L++) {
    const float* Wh = (const float*)d_in[2 + 4 * L + 0];
    const float* ah = (const float*)d_in[2 + 4 * L + 1];
    const float* Wo = (const float*)d_in[2 + 4 * L + 2];
    const float* ao = (const float*)d_in[2 + 4 * L + 3];
    int fin = FIN[L], hid = HID[L], fout = FOUT[L];

    // per-head weights: transpose+split to [H][hid, fin] (coalesced)
    split_tr<<<dim3(hid / 32, fin / 32, NH), dim3(32, 8)>>>(Wh, p_bH, p_bL, fin, hid);
    // h[head] = cur @ Wh[head]  -> [H, N, hid]  (HMMA, batched over heads)
    gemm_mma<<<dim3(hid / 128, NN / 128, NH), 256, GSM_TOTAL>>>(
        p_aH, p_aL, p_bH, p_bL, p_h, hid, fin,
        (long long)fin * hid, (long long)NN * hid, 1, 0);
    // s1/s2 per head
    rowdot2<<<dim3(NN / 8, NH), 256>>>(p_h, ah, p_s1, p_s2, hid);
    // sparse attention + elu -> hcat split-bf16 directly into aH/aL [N, 8*hid]
    attn_agg<<<dim3(NN, NH), 128>>>(p_rowptr, p_cols, p_s1, p_s2, p_h,
                                    (float*)nullptr, p_aH, p_aL,
                                    hid, (long long)NH * hid);
    // output weights: transpose+split to [fout, 8*hid]
    split_tr<<<dim3(fout / 32, (NH * hid) / 32, 1), dim3(32, 8)>>>(Wo, p_bH, p_bL,
                                                                   NH * hid, fout);
    // ho = hcat @ Wo -> [N, fout]  via split-K 8 (deterministic reduce)
    gemm_mma<<<dim3(fout / 128, NN / 128, 8), 256, GSM_TOTAL>>>(
        p_aH, p_aL, p_bH, p_bL, p_part, fout, NH * hid,
        0, 0, 8, (long long)NN * fout);
    {
      long long n = (long long)NN * fout;
      reduce8<<<(unsigned)((n + 255) / 256), 256>>>(p_part, p_ho, n,
                                                    (long long)NN * fout);
    }
    // output-head scores
    rowdot2<<<dim3(NN / 8, 1), 256>>>(p_ho, ao, p_t1, p_t2, fout);
    // output sparse attention + elu:
    //   L<5: write next-layer features as split-bf16 directly (no fp32 pass)
    //   L=5: write final fp32 output
    if (L == 5) {
      attn_agg<<<dim3(NN, 1), 128>>>(p_rowptr, p_cols, p_t1, p_t2, p_ho,
                                     (float*)d_out, (__nv_bfloat16*)nullptr,
                                     (__nv_bfloat16*)nullptr, fout, (long long)fout);
    } else {
      attn_agg<<<dim3(NN, 1), 128>>>(p_rowptr, p_cols, p_t1, p_t2, p_ho,
                                     (float*)nullptr, p_aH, p_aL,
                                     fout, (long long)fout);
    }
  }
}